// round 2
// baseline (speedup 1.0000x reference)
#include <cuda_runtime.h>
#include <math.h>
#include <float.h>

// ---------------- problem constants ----------------
#define HID    256
#define BS     64
#define DCS    16
#define NCLASS 60
#define QSIZE  5
#define TOPK   5
#define TOPKQ  100
#define NROWS  (BS * DCS)             // 1024 query rows
#define NKEY   (NCLASS * DCS)         // 960 memory-key rows
#define NKQ    (NCLASS * QSIZE * DCS) // 4800 queue-key rows
#define CAND   (TOPK * QSIZE * DCS)   // 400 candidates per row

// ---------------- scratch (no cudaMalloc allowed) ----------------
__device__ __align__(16) float g_key[NKEY * HID];        // transformed memory keys
__device__ __align__(16) float g_query[NROWS * HID];
__device__ __align__(16) float g_qq[NROWS * HID];
__device__ __align__(16) float g_kqK[NKQ * HID];         // transformed queue keys (computed ONCE)
__device__ __align__(16) float g_weights[NROWS * NKEY];  // 1024 x 960 similarity
__device__ __align__(16) float g_zcat[NROWS * 2 * HID];  // [queue | memory_z]
__device__ int g_cls[NROWS * TOPK];

// ---------------- 64x64 fp32 SGEMM tile:  C = A * B^T (+bias) ----------------
// A: MxK row-major, B: NxK row-major (K-contiguous both), C: MxN.
// All M,N multiples of 64; K multiple of 16. 256 threads/block.
#define BKT 16
__device__ __forceinline__ void sgemm_tile(const float* __restrict__ A,
                                           const float* __restrict__ B,
                                           const float* __restrict__ bias,
                                           float* __restrict__ C,
                                           int K, int N, int mb, int nb) {
    __shared__ float As[BKT][68];   // transposed tiles, +4 pad keeps float4 rows 16B-aligned
    __shared__ float Bs[BKT][68];

    const int tid  = threadIdx.x;           // 256
    const int tm   = tid >> 4;              // 0..15
    const int tn   = tid & 15;              // 0..15
    const int lrow = tid >> 2;              // 0..63
    const int lcol = (tid & 3) << 2;        // 0,4,8,12

    const float* Ap = A + (size_t)(mb * 64 + lrow) * K + lcol;
    const float* Bp = B + (size_t)(nb * 64 + lrow) * K + lcol;

    float acc[4][4];
#pragma unroll
    for (int i = 0; i < 4; i++)
#pragma unroll
        for (int j = 0; j < 4; j++) acc[i][j] = 0.0f;

    for (int k0 = 0; k0 < K; k0 += BKT) {
        float4 av = *(const float4*)(Ap + k0);
        float4 bv = *(const float4*)(Bp + k0);
        As[lcol + 0][lrow] = av.x; As[lcol + 1][lrow] = av.y;
        As[lcol + 2][lrow] = av.z; As[lcol + 3][lrow] = av.w;
        Bs[lcol + 0][lrow] = bv.x; Bs[lcol + 1][lrow] = bv.y;
        Bs[lcol + 2][lrow] = bv.z; Bs[lcol + 3][lrow] = bv.w;
        __syncthreads();
#pragma unroll
        for (int kk = 0; kk < BKT; kk++) {
            float4 a4 = *(const float4*)&As[kk][tm * 4];
            float4 b4 = *(const float4*)&Bs[kk][tn * 4];
            float a[4] = {a4.x, a4.y, a4.z, a4.w};
            float b[4] = {b4.x, b4.y, b4.z, b4.w};
#pragma unroll
            for (int i = 0; i < 4; i++)
#pragma unroll
                for (int j = 0; j < 4; j++) acc[i][j] = fmaf(a[i], b[j], acc[i][j]);
        }
        __syncthreads();
    }

    float bb[4] = {0.f, 0.f, 0.f, 0.f};
    const int cn = nb * 64 + tn * 4;
    if (bias) {
#pragma unroll
        for (int j = 0; j < 4; j++) bb[j] = bias[cn + j];
    }
#pragma unroll
    for (int i = 0; i < 4; i++) {
        float4 o;
        o.x = acc[i][0] + bb[0]; o.y = acc[i][1] + bb[1];
        o.z = acc[i][2] + bb[2]; o.w = acc[i][3] + bb[3];
        *(float4*)(C + (size_t)(mb * 64 + tm * 4 + i) * N + cn) = o;
    }
}

// Fused: key = memory_key@key_w^T+b (960x256), query = h@query_w^T+b, qq = h@qq_w^T+b
__global__ void lin3_kernel(const float* __restrict__ h, const float* __restrict__ memk,
                            const float* __restrict__ key_w, const float* __restrict__ key_b,
                            const float* __restrict__ query_w, const float* __restrict__ query_b,
                            const float* __restrict__ qq_w, const float* __restrict__ qq_b) {
    int by = blockIdx.y;
    if (by < 15)       sgemm_tile(memk, key_w,   key_b,   g_key,   HID, HID, by,      blockIdx.x);
    else if (by < 31)  sgemm_tile(h,    query_w, query_b, g_query, HID, HID, by - 15, blockIdx.x);
    else               sgemm_tile(h,    qq_w,    qq_b,    g_qq,    HID, HID, by - 31, blockIdx.x);
}

// queue-key transform: g_kqK = queue_key @ kq_w^T + kq_b  (4800 x 256)
__global__ void kq_transform_kernel(const float* __restrict__ queue_key,
                                    const float* __restrict__ kq_w,
                                    const float* __restrict__ kq_b) {
    sgemm_tile(queue_key, kq_w, kq_b, g_kqK, HID, HID, blockIdx.y, blockIdx.x);
}

// similarity: g_weights = g_query @ g_key^T  (1024 x 960)
__global__ void sim_kernel() {
    sgemm_tile(g_query, g_key, nullptr, g_weights, HID, NKEY, blockIdx.y, blockIdx.x);
}

// fusion: out = g_zcat @ proto_w^T + proto_b  (1024 x 256, K=512)
__global__ void out_kernel(const float* __restrict__ proto_w,
                           const float* __restrict__ proto_b,
                           float* __restrict__ out) {
    sgemm_tile(g_zcat, proto_w, proto_b, out, 2 * HID, HID, blockIdx.y, blockIdx.x);
}

// ---------------- top-5 over 960 + softmax + weighted key gather ----------------
__global__ void top5_kernel() {
    const int n = blockIdx.x, tid = threadIdx.x; // 256 threads
    __shared__ float s[NKEY];
    __shared__ float rv[256];
    __shared__ int   ri[256];
    __shared__ float w5[TOPK], p5[TOPK];
    __shared__ int   i5[TOPK];

    for (int i = tid; i < NKEY; i += 256) s[i] = g_weights[n * NKEY + i];
    __syncthreads();

    for (int it = 0; it < TOPK; it++) {
        float bv = -FLT_MAX; int bi = 0;
        for (int i = tid; i < NKEY; i += 256)
            if (s[i] > bv) { bv = s[i]; bi = i; }
        rv[tid] = bv; ri[tid] = bi;
        __syncthreads();
        for (int off = 128; off > 0; off >>= 1) {
            if (tid < off && rv[tid + off] > rv[tid]) { rv[tid] = rv[tid + off]; ri[tid] = ri[tid + off]; }
            __syncthreads();
        }
        if (tid == 0) { w5[it] = rv[0]; i5[it] = ri[0]; s[ri[0]] = -FLT_MAX; }
        __syncthreads();
    }

    if (tid == 0) {
        float m = w5[0], sum = 0.f, e[TOPK];
#pragma unroll
        for (int j = 0; j < TOPK; j++) { e[j] = expf(w5[j] - m); sum += e[j]; }
#pragma unroll
        for (int j = 0; j < TOPK; j++) p5[j] = e[j] / sum;
    }
    if (tid < TOPK) g_cls[n * TOPK + tid] = i5[tid] / DCS;
    __syncthreads();

    // memory_z -> second half of zcat
    float acc = 0.f;
#pragma unroll
    for (int j = 0; j < TOPK; j++) acc = fmaf(p5[j], g_key[i5[j] * HID + tid], acc);
    g_zcat[n * (2 * HID) + HID + tid] = acc;
}

// ---------------- level-2 queue retrieval ----------------
__device__ __forceinline__ unsigned long long packkv(float v, int idx) {
    unsigned u = __float_as_uint(v);
    u = (u & 0x80000000u) ? ~u : (u | 0x80000000u);
    return ((unsigned long long)u << 32) | (unsigned)idx;
}
__device__ __forceinline__ float unpackv(unsigned long long kv) {
    unsigned u = (unsigned)(kv >> 32);
    u = (u & 0x80000000u) ? (u & 0x7FFFFFFFu) : ~u;
    return __uint_as_float(u);
}

__global__ void queue_kernel() {
    const int n = blockIdx.x, tid = threadIdx.x; // 256 threads
    __shared__ __align__(16) float q_s[HID];
    __shared__ unsigned long long kv[512];
    __shared__ int   clsn[TOPK];
    __shared__ float pex[TOPKQ];
    __shared__ int   growA[TOPKQ];
    __shared__ float s_sum;

    q_s[tid] = g_qq[n * HID + tid];
    if (tid < TOPK) clsn[tid] = g_cls[n * TOPK + tid];
    for (int i = CAND + tid; i < 512; i += 256) kv[i] = 0ull; // pads sort to the bottom
    __syncthreads();

    // 400 dot products, warp-per-dot (fully coalesced float4 reads)
    const int warp = tid >> 5, lane = tid & 31;
    const float4* q4 = (const float4*)q_s;
    float4 qa = q4[lane], qb = q4[32 + lane];
    for (int m = warp; m < CAND; m += 8) {
        const int grow = clsn[m / 80] * 80 + (m % 80);
        const float4* r4 = (const float4*)(g_kqK + (size_t)grow * HID);
        float4 a = r4[lane], b = r4[32 + lane];
        float acc = a.x * qa.x + a.y * qa.y + a.z * qa.z + a.w * qa.w
                  + b.x * qb.x + b.y * qb.y + b.z * qb.z + b.w * qb.w;
#pragma unroll
        for (int off = 16; off > 0; off >>= 1) acc += __shfl_xor_sync(0xffffffffu, acc, off);
        if (lane == 0) kv[m] = packkv(acc, m);
    }
    __syncthreads();

    // bitonic sort 512, descending
    for (int k = 2; k <= 512; k <<= 1) {
        for (int j = k >> 1; j > 0; j >>= 1) {
            for (int i = tid; i < 512; i += 256) {
                int ixj = i ^ j;
                if (ixj > i) {
                    unsigned long long a = kv[i], b = kv[ixj];
                    if ((a < b) == ((i & k) == 0)) { kv[i] = b; kv[ixj] = a; }
                }
            }
            __syncthreads();
        }
    }

    // softmax over top-100 + weighted gather of pre-transformed queue keys
    float maxv = unpackv(kv[0]);
    if (tid < TOPKQ) {
        unsigned long long e = kv[tid];
        pex[tid] = expf(unpackv(e) - maxv);
        int m = (int)(e & 0xFFFFFFFFull);
        growA[tid] = (clsn[m / 80] * 80 + (m % 80)) * HID;
    }
    __syncthreads();
    if (tid == 0) {
        float ss = 0.f;
        for (int i = 0; i < TOPKQ; i++) ss += pex[i];
        s_sum = ss;
    }
    __syncthreads();

    float acc = 0.f;
#pragma unroll 4
    for (int i = 0; i < TOPKQ; i++) acc = fmaf(pex[i], g_kqK[growA[i] + tid], acc);
    g_zcat[n * (2 * HID) + tid] = acc * (1.0f / s_sum);
}

// ---------------- launch: pure kernel-launch sequence (graph-capture safe) ----------------
extern "C" void kernel_launch(void* const* d_in, const int* in_sizes, int n_in,
                              void* d_out, int out_size) {
    const float* h          = (const float*)d_in[0];  // (64,16,256)
    // d_in[1] labels, d_in[2] tag : unused
    const float* memory_key = (const float*)d_in[3];  // (60,16,256)
    const float* queue_key  = (const float*)d_in[4];  // (60,5,16,256)
    const float* key_w   = (const float*)d_in[5];
    const float* key_b   = (const float*)d_in[6];
    const float* query_w = (const float*)d_in[7];
    const float* query_b = (const float*)d_in[8];
    const float* kq_w    = (const float*)d_in[9];
    const float* kq_b    = (const float*)d_in[10];
    const float* qq_w    = (const float*)d_in[11];
    const float* qq_b    = (const float*)d_in[12];
    const float* proto_w = (const float*)d_in[13];    // (256, 512)
    const float* proto_b = (const float*)d_in[14];
    float* out = (float*)d_out;                       // (64,16,256)

    // 1) input-side linears (key / query / qq) fused in one launch
    lin3_kernel<<<dim3(4, 47), 256>>>(h, memory_key, key_w, key_b, query_w, query_b, qq_w, qq_b);
    // 2) transform ALL 4800 queue keys once (reference redundantly does this post-gather: 53.7 GF -> 0.63 GF)
    kq_transform_kernel<<<dim3(4, NKQ / 64), 256>>>(queue_key, kq_w, kq_b);
    // 3) similarity: weights = query @ key^T  (1024 x 960)
    sim_kernel<<<dim3(NKEY / 64, NROWS / 64), 256>>>();
    // 4) top-5 + softmax + memory_z (+ class indices)
    top5_kernel<<<NROWS, 256>>>();
    // 5) queue scoring, exact top-100 via bitonic sort, softmax, gather
    queue_kernel<<<NROWS, 256>>>();
    // 6) fusion: out = [queue | memory_z] @ proto_w^T + proto_b
    out_kernel<<<dim3(HID / 64, NROWS / 64), 256>>>(proto_w, proto_b, out);
}

// round 4
// speedup vs baseline: 1.0988x; 1.0988x over previous
#include <cuda_runtime.h>
#include <math.h>
#include <float.h>

// ---------------- problem constants ----------------
#define HID    256
#define BS     64
#define DCS    16
#define NCLASS 60
#define QSIZE  5
#define TOPK   5
#define TOPKQ  100
#define NROWS  (BS * DCS)             // 1024 query rows
#define NKEY   (NCLASS * DCS)         // 960 memory-key rows
#define NKQ    (NCLASS * QSIZE * DCS) // 4800 queue-key rows
#define CAND   (TOPK * QSIZE * DCS)   // 400 candidates per row

// ---------------- scratch ----------------
__device__ __align__(16) float g_key[NKEY * HID];
__device__ __align__(16) float g_query[NROWS * HID];
__device__ __align__(16) float g_qq[NROWS * HID];
__device__ __align__(16) float g_kqK[NKQ * HID];
__device__ __align__(16) float g_weights[NROWS * NKEY];
__device__ __align__(16) float g_zcat[NROWS * 2 * HID];

// ---------------- f32x2 helpers ----------------
__device__ __forceinline__ unsigned long long pkdup(float a) {
    unsigned long long r; unsigned u = __float_as_uint(a);
    asm("mov.b64 %0, {%1, %1};" : "=l"(r) : "r"(u));
    return r;
}
__device__ __forceinline__ float2 unpk(unsigned long long v) {
    float2 r;
    asm("mov.b64 {%0, %1}, %2;" : "=f"(r.x), "=f"(r.y) : "l"(v));
    return r;
}

// ---------------- 64x64 SGEMM tile via fma.rn.f32x2 ----------------
// C = A * B^T (+bias). A: MxK, B: NxK row-major. 64 threads, 8x8 per thread.
// M,N multiples of 64; K multiple of 16.
__device__ __forceinline__ void sgemm64(const float* __restrict__ A,
                                        const float* __restrict__ B,
                                        const float* __restrict__ bias,
                                        float* __restrict__ C,
                                        int K, int N, int mb, int nb) {
    __shared__ __align__(16) float As[16][68];   // [k][m], row stride 272B -> 16B-aligned rows
    __shared__ __align__(16) float Bs[16][68];   // [k][n]

    const int tid  = threadIdx.x;     // 64
    const int tm   = tid >> 3;        // 0..7  -> rows tm*4+{0..3}, +32
    const int tn   = tid & 7;         // 0..7  -> cols tn*4+{0..3}, +32
    const int lrow = tid >> 2;        // 0..15
    const int lcol = (tid & 3) << 2;  // 0,4,8,12

    const float* Ap = A + (size_t)(mb * 64 + lrow) * K + lcol;
    const float* Bp = B + (size_t)(nb * 64 + lrow) * K + lcol;

    unsigned long long acc[32];
#pragma unroll
    for (int i = 0; i < 32; i++) acc[i] = 0ull;

    float4 av[4], bv[4];
#pragma unroll
    for (int r = 0; r < 4; r++) {
        av[r] = *(const float4*)(Ap + (size_t)(r * 16) * K);
        bv[r] = *(const float4*)(Bp + (size_t)(r * 16) * K);
    }

    for (int k0 = 0; k0 < K; k0 += 16) {
#pragma unroll
        for (int r = 0; r < 4; r++) {
            As[lcol + 0][lrow + r * 16] = av[r].x;
            As[lcol + 1][lrow + r * 16] = av[r].y;
            As[lcol + 2][lrow + r * 16] = av[r].z;
            As[lcol + 3][lrow + r * 16] = av[r].w;
            Bs[lcol + 0][lrow + r * 16] = bv[r].x;
            Bs[lcol + 1][lrow + r * 16] = bv[r].y;
            Bs[lcol + 2][lrow + r * 16] = bv[r].z;
            Bs[lcol + 3][lrow + r * 16] = bv[r].w;
        }
        __syncthreads();

        if (k0 + 16 < K) {
#pragma unroll
            for (int r = 0; r < 4; r++) {
                av[r] = *(const float4*)(Ap + (size_t)(r * 16) * K + k0 + 16);
                bv[r] = *(const float4*)(Bp + (size_t)(r * 16) * K + k0 + 16);
            }
        }

#pragma unroll
        for (int kk = 0; kk < 16; kk++) {
            float4 a0 = *(const float4*)&As[kk][tm * 4];
            float4 a1 = *(const float4*)&As[kk][tm * 4 + 32];
            ulonglong2 bl0 = *(const ulonglong2*)&Bs[kk][tn * 4];
            ulonglong2 bl1 = *(const ulonglong2*)&Bs[kk][tn * 4 + 32];
            float av8[8] = {a0.x, a0.y, a0.z, a0.w, a1.x, a1.y, a1.z, a1.w};
            unsigned long long bb[4] = {bl0.x, bl0.y, bl1.x, bl1.y};
#pragma unroll
            for (int i = 0; i < 8; i++) {
                unsigned long long aa = pkdup(av8[i]);
#pragma unroll
                for (int j = 0; j < 4; j++)
                    asm("fma.rn.f32x2 %0, %1, %2, %0;" : "+l"(acc[i * 4 + j]) : "l"(aa), "l"(bb[j]));
            }
        }
        __syncthreads();
    }

    const int cn = nb * 64 + tn * 4;
    float4 b0 = make_float4(0.f, 0.f, 0.f, 0.f), b1 = b0;
    if (bias) {
        b0 = *(const float4*)(bias + cn);
        b1 = *(const float4*)(bias + cn + 32);
    }
#pragma unroll
    for (int i = 0; i < 8; i++) {
        const int r2 = mb * 64 + tm * 4 + ((i < 4) ? i : (32 + i - 4));
        float2 c0 = unpk(acc[i * 4 + 0]);
        float2 c1 = unpk(acc[i * 4 + 1]);
        float2 c2 = unpk(acc[i * 4 + 2]);
        float2 c3 = unpk(acc[i * 4 + 3]);
        float4 o0 = make_float4(c0.x + b0.x, c0.y + b0.y, c1.x + b0.z, c1.y + b0.w);
        float4 o1 = make_float4(c2.x + b1.x, c2.y + b1.y, c3.x + b1.z, c3.y + b1.w);
        *(float4*)(C + (size_t)r2 * N + cn)      = o0;
        *(float4*)(C + (size_t)r2 * N + cn + 32) = o1;
    }
}

// ---------------- fused: key / query / qq / kq transforms ----------------
__global__ void __launch_bounds__(64) prep_kernel(
        const float* __restrict__ h, const float* __restrict__ memk,
        const float* __restrict__ queue_key,
        const float* __restrict__ key_w, const float* __restrict__ key_b,
        const float* __restrict__ query_w, const float* __restrict__ query_b,
        const float* __restrict__ qq_w, const float* __restrict__ qq_b,
        const float* __restrict__ kq_w, const float* __restrict__ kq_b) {
    int by = blockIdx.y;
    if (by < 15)       sgemm64(memk,      key_w,   key_b,   g_key,   HID, HID, by,      blockIdx.x);
    else if (by < 31)  sgemm64(h,         query_w, query_b, g_query, HID, HID, by - 15, blockIdx.x);
    else if (by < 47)  sgemm64(h,         qq_w,    qq_b,    g_qq,    HID, HID, by - 31, blockIdx.x);
    else               sgemm64(queue_key, kq_w,    kq_b,    g_kqK,   HID, HID, by - 47, blockIdx.x);
}

// similarity: g_weights = g_query @ g_key^T  (1024 x 960)
__global__ void __launch_bounds__(64) sim_kernel() {
    sgemm64(g_query, g_key, nullptr, g_weights, HID, NKEY, blockIdx.y, blockIdx.x);
}

// fusion: out = g_zcat @ proto_w^T + proto_b  (1024 x 256, K=512)
__global__ void __launch_bounds__(64) out_kernel(const float* __restrict__ proto_w,
                                                 const float* __restrict__ proto_b,
                                                 float* __restrict__ out) {
    sgemm64(g_zcat, proto_w, proto_b, out, 2 * HID, HID, blockIdx.y, blockIdx.x);
}

// ---------------- packed (value,index) helpers ----------------
__device__ __forceinline__ unsigned long long packkv(float v, int idx) {
    unsigned u = __float_as_uint(v);
    u = (u & 0x80000000u) ? ~u : (u | 0x80000000u);
    return ((unsigned long long)u << 32) | (unsigned)idx;
}
__device__ __forceinline__ float unpackv(unsigned long long kv) {
    unsigned u = (unsigned)(kv >> 32);
    u = (u & 0x80000000u) ? (u & 0x7FFFFFFFu) : ~u;
    return __uint_as_float(u);
}

// ---------------- fused top-5 + memory_z + queue retrieval (per row) ----------------
__global__ void __launch_bounds__(256) retrieve_kernel() {
    const int n = blockIdx.x, tid = threadIdx.x;
    const int warp = tid >> 5, lane = tid & 31;

    __shared__ __align__(16) float q_s[HID];
    __shared__ unsigned long long kv[512];
    __shared__ unsigned long long wred[8];
    __shared__ float w5[TOPK];
    __shared__ int   i5[TOPK], clsn[TOPK];
    __shared__ float pex[TOPKQ];
    __shared__ int   growA[TOPKQ];
    __shared__ float s_sum;

    q_s[tid] = g_qq[n * HID + tid];
    for (int i = CAND + tid; i < 512; i += 256) kv[i] = 0ull;

    // ---- phase A: top-5 over 960 scores, register-resident candidates ----
    const float* wrow = g_weights + (size_t)n * NKEY;
    float v[4];
    v[0] = wrow[tid];
    v[1] = wrow[tid + 256];
    v[2] = wrow[tid + 512];
    v[3] = (tid < 192) ? wrow[tid + 768] : -FLT_MAX;

    for (int it = 0; it < TOPK; it++) {
        unsigned long long best = packkv(v[0], tid);
        best = max(best, packkv(v[1], tid + 256));
        best = max(best, packkv(v[2], tid + 512));
        best = max(best, packkv(v[3], tid + 768));
#pragma unroll
        for (int off = 16; off > 0; off >>= 1)
            best = max(best, __shfl_down_sync(0xffffffffu, best, off));
        if (lane == 0) wred[warp] = best;
        __syncthreads();
        if (warp == 0) {
            unsigned long long b = (lane < 8) ? wred[lane] : 0ull;
#pragma unroll
            for (int off = 4; off > 0; off >>= 1)
                b = max(b, __shfl_down_sync(0xffffffffu, b, off));
            if (lane == 0) {
                int idx = (int)(b & 0xFFFFFFFFull);
                w5[it] = unpackv(b); i5[it] = idx; clsn[it] = idx / DCS;
                wred[0] = b;
            }
        }
        __syncthreads();
        int widx = (int)(wred[0] & 0xFFFFFFFFull);
        if ((widx & 255) == tid) v[widx >> 8] = -FLT_MAX;
        __syncthreads();
    }

    // softmax over top-5 + memory_z (all threads, col = tid)
    {
        float m = w5[0], e[TOPK], sum = 0.f;
#pragma unroll
        for (int j = 0; j < TOPK; j++) { e[j] = expf(w5[j] - m); sum += e[j]; }
        float inv = 1.0f / sum;
        float acc = 0.f;
#pragma unroll
        for (int j = 0; j < TOPK; j++) acc = fmaf(e[j] * inv, g_key[i5[j] * HID + tid], acc);
        g_zcat[n * (2 * HID) + HID + tid] = acc;
    }

    // ---- phase B: queue scoring (400 dots, warp-per-dot) ----
    __syncthreads();
    const float4* q4 = (const float4*)q_s;
    float4 qa = q4[lane], qb = q4[32 + lane];
    for (int m = warp; m < CAND; m += 8) {
        const int grow = clsn[m / 80] * 80 + (m % 80);
        const float4* r4 = (const float4*)(g_kqK + (size_t)grow * HID);
        float4 a = r4[lane], b = r4[32 + lane];
        float acc = a.x * qa.x + a.y * qa.y + a.z * qa.z + a.w * qa.w
                  + b.x * qb.x + b.y * qb.y + b.z * qb.z + b.w * qb.w;
#pragma unroll
        for (int off = 16; off > 0; off >>= 1) acc += __shfl_xor_sync(0xffffffffu, acc, off);
        if (lane == 0) kv[m] = packkv(acc, m);
    }
    __syncthreads();

    // bitonic sort 512 descending
    for (int k = 2; k <= 512; k <<= 1) {
        for (int j = k >> 1; j > 0; j >>= 1) {
            for (int i = tid; i < 512; i += 256) {
                int ixj = i ^ j;
                if (ixj > i) {
                    unsigned long long a = kv[i], b = kv[ixj];
                    if ((a < b) == ((i & k) == 0)) { kv[i] = b; kv[ixj] = a; }
                }
            }
            __syncthreads();
        }
    }

    // softmax over top-100 + weighted gather
    float maxv = unpackv(kv[0]);
    if (tid < TOPKQ) {
        unsigned long long e = kv[tid];
        pex[tid] = expf(unpackv(e) - maxv);
        int m = (int)(e & 0xFFFFFFFFull);
        growA[tid] = (clsn[m / 80] * 80 + (m % 80)) * HID;
    }
    __syncthreads();
    if (tid == 0) {
        float ss = 0.f;
        for (int i = 0; i < TOPKQ; i++) ss += pex[i];
        s_sum = ss;
    }
    __syncthreads();

    float acc = 0.f;
#pragma unroll 4
    for (int i = 0; i < TOPKQ; i++) acc = fmaf(pex[i], g_kqK[growA[i] + tid], acc);
    g_zcat[n * (2 * HID) + tid] = acc * (1.0f / s_sum);
}

// ---------------- launch ----------------
extern "C" void kernel_launch(void* const* d_in, const int* in_sizes, int n_in,
                              void* d_out, int out_size) {
    const float* h          = (const float*)d_in[0];
    const float* memory_key = (const float*)d_in[3];
    const float* queue_key  = (const float*)d_in[4];
    const float* key_w   = (const float*)d_in[5];
    const float* key_b   = (const float*)d_in[6];
    const float* query_w = (const float*)d_in[7];
    const float* query_b = (const float*)d_in[8];
    const float* kq_w    = (const float*)d_in[9];
    const float* kq_b    = (const float*)d_in[10];
    const float* qq_w    = (const float*)d_in[11];
    const float* qq_b    = (const float*)d_in[12];
    const float* proto_w = (const float*)d_in[13];
    const float* proto_b = (const float*)d_in[14];
    float* out = (float*)d_out;

    // 1) all four input-side linears in one launch (488 blocks)
    prep_kernel<<<dim3(4, 122), 64>>>(h, memory_key, queue_key,
                                      key_w, key_b, query_w, query_b,
                                      qq_w, qq_b, kq_w, kq_b);
    // 2) similarity 1024x960
    sim_kernel<<<dim3(NKEY / 64, NROWS / 64), 64>>>();
    // 3) fused top-5 + memory_z + queue retrieval
    retrieve_kernel<<<NROWS, 256>>>();
    // 4) fusion GEMM -> out
    out_kernel<<<dim3(HID / 64, NROWS / 64), 64>>>(proto_w, proto_b, out);
}